// round 15
// baseline (speedup 1.0000x reference)
#include <cuda_runtime.h>
#include <cuda_bf16.h>
#include <cuda_fp16.h>
#include <math.h>
#include <stdint.h>

#define B_   4
#define S_   2048
#define D_   1024
#define H_   16
#define DEP_ 64
#define DFF_ 4096
#define M_   (B_ * S_)
#define EPS_ 1e-6f
#define QSC_ 0.180336884f   /* 0.125 * log2(e) */

// ---------------- scratch (static device globals) ----------------
__device__ __half g_xh[M_ * D_];
__device__ __half g_wqkvT[3 * D_ * D_];
__device__ float  g_bqkv[3 * D_];
__device__ __half g_woT[D_ * D_];
__device__ __half g_w1T[DFF_ * D_];
__device__ __half g_w2T[D_ * DFF_];
__device__ __half g_qh[M_ * D_];
__device__ __half g_kh[M_ * D_];
__device__ __half g_vh[M_ * D_];
__device__ float  g_mask2[B_ * S_];
__device__ __half g_ctxh[M_ * D_];
__device__ __half g_tmph[M_ * D_];
__device__ float  g_o1[M_ * D_];
__device__ __half g_o1h[M_ * D_];
__device__ __half g_ffnh[M_ * DFF_];

// ---------------- PTX helpers (base-arch only) ----------------
__device__ __forceinline__ uint32_t smem_u32(const void* p) {
    uint32_t a;
    asm("{ .reg .u64 t; cvta.to.shared.u64 t, %1; cvt.u32.u64 %0, t; }" : "=r"(a) : "l"(p));
    return a;
}
__device__ __forceinline__ void cp_async16(uint32_t dst, const void* src) {
    asm volatile("cp.async.cg.shared.global [%0], [%1], 16;" :: "r"(dst), "l"(src));
}
__device__ __forceinline__ void cp_async4(uint32_t dst, const void* src) {
    asm volatile("cp.async.ca.shared.global [%0], [%1], 4;" :: "r"(dst), "l"(src));
}
__device__ __forceinline__ void cp_commit() {
    asm volatile("cp.async.commit_group;" ::: "memory");
}
#define LDMX4(r, addr)                                                           \
    asm volatile("ldmatrix.sync.aligned.m8n8.x4.shared.b16 {%0,%1,%2,%3}, [%4];" \
        : "=r"((r)[0]), "=r"((r)[1]), "=r"((r)[2]), "=r"((r)[3]) : "r"(addr))
#define LDMX4T(r, addr)                                                          \
    asm volatile("ldmatrix.sync.aligned.m8n8.x4.trans.shared.b16 {%0,%1,%2,%3}, [%4];" \
        : "=r"((r)[0]), "=r"((r)[1]), "=r"((r)[2]), "=r"((r)[3]) : "r"(addr))
#define MMAF16(d, a, b0, b1)                                                     \
    asm volatile("mma.sync.aligned.m16n8k16.row.col.f32.f16.f16.f32 "            \
        "{%0,%1,%2,%3}, {%4,%5,%6,%7}, {%8,%9}, {%0,%1,%2,%3};"                  \
        : "+f"((d)[0]), "+f"((d)[1]), "+f"((d)[2]), "+f"((d)[3])                 \
        : "r"((a)[0]), "r"((a)[1]), "r"((a)[2]), "r"((a)[3]), "r"(b0), "r"(b1))

__device__ __forceinline__ uint32_t pack_h2(float a, float b) {
    __half2 v = __floats2half2_rn(a, b);
    return *reinterpret_cast<uint32_t*>(&v);
}
// fast 2^t on the FMA pipe (no MUFU); rel err ~4e-5
__device__ __forceinline__ float fexp2(float t) {
    t = fmaxf(t, -126.f);
    float r = t + 12582912.f;
    float f = t - (r - 12582912.f);
    uint32_t ib = (__float_as_uint(r) << 23) + 0x3F800000u;
    float p = fmaf(f, 0.00961813f, 0.05550411f);
    p = fmaf(f, p, 0.24022651f);
    p = fmaf(f, p, 0.69314718f);
    p = fmaf(f, p, 1.0f);
    return __uint_as_float(ib) * p;
}

// ---------------------------------------------------------------------------
// single-fp16 GEMM: C = A[M,K] @ B^T[N,K] + bias, 1 MMA/step.
// Tile 64x128 x K64, 2-stage pipeline; 128 threads, 2x2 warp grid (32x64
// warp tiles). NOW reg-capped for 4 CTAs/SM (16 warps) to fill chunk-boundary
// bubbles (R14 profile: tensor 58.6%, occ 16.9%).
// Stage (24KB): A(8K) | B(16K); 128B rows, XOR-swizzled.
// MODE: 0 = fp16 out; 1 = relu + fp16 out; 2 = fused-QKV epilogue.
// ---------------------------------------------------------------------------
#define ST_       24576
#define GEMM_SMEM (2 * ST_)

template <int MODE>
__global__ __launch_bounds__(128, 4)
void gemm_mma(const __half* __restrict__ A, const __half* __restrict__ Bw,
              const float* __restrict__ bias,
              __half* __restrict__ Ch,
              __half* __restrict__ Qh, __half* __restrict__ Kh, __half* __restrict__ Vh,
              int M, int N, int K)
{
    extern __shared__ char smem[];
    const uint32_t sb = smem_u32(smem);
    const int tid  = threadIdx.x;
    const int wid  = tid >> 5;
    const int lane = tid & 31;

    const int rowA  = blockIdx.y * 64;
    const int rowBn = blockIdx.x * 128;
    const int CH    = K >> 6;

    auto issue_loads = [&](int c) {
        const int k0 = c << 6;
        const uint32_t stg = sb + (uint32_t)(c & 1) * ST_;
        #pragma unroll
        for (int j = 0; j < 12; j++) {
            const __half* base;
            uint32_t doff;
            int rel, rb;
            if (j < 4) { base = A;  doff = 0u;    rel = j * 128 + tid;       rb = rowA;  }
            else       { base = Bw; doff = 8192u; rel = (j - 4) * 128 + tid; rb = rowBn; }
            const int row = rel >> 3, c16 = rel & 7;
            const uint32_t off = (uint32_t)(row * 128) + ((uint32_t)(c16 ^ (row & 7)) << 4);
            cp_async16(stg + doff + off, base + (size_t)(rb + row) * K + k0 + c16 * 8);
        }
        cp_commit();
    };

    issue_loads(0);
    issue_loads(1);

    float acc[2][8][4];
    #pragma unroll
    for (int i = 0; i < 2; i++)
        #pragma unroll
        for (int j = 0; j < 8; j++)
            #pragma unroll
            for (int r = 0; r < 4; r++) acc[i][j][r] = 0.f;

    const int wm = (wid >> 1) * 32;   // 2 warp rows x 32
    const int wn = (wid & 1) * 64;    // 2 warp cols x 64
    const int l7 = lane & 7;
    const int mi = lane >> 3;

    for (int c = 0; c < CH; c++) {
        if (c + 1 < CH) { asm volatile("cp.async.wait_group 1;" ::: "memory"); }
        else            { asm volatile("cp.async.wait_group 0;" ::: "memory"); }
        __syncthreads();

        const uint32_t stg = sb + (uint32_t)(c & 1) * ST_;
        #pragma unroll
        for (int ks = 0; ks < 4; ks++) {
            uint32_t ah[2][4], bh[4][4];
            #pragma unroll
            for (int mt = 0; mt < 2; mt++) {
                const int r = wm + mt * 16 + l7 + ((mi & 1) << 3);
                const uint32_t cc = (uint32_t)((2 * ks + (mi >> 1)) ^ (r & 7));
                LDMX4(ah[mt], stg + (uint32_t)(r * 128) + (cc << 4));
            }
            #pragma unroll
            for (int p = 0; p < 4; p++) {
                const int r = wn + p * 16 + l7 + ((mi >> 1) << 3);
                const uint32_t cc = (uint32_t)((2 * ks + (mi & 1)) ^ (r & 7));
                LDMX4(bh[p], stg + 8192u + (uint32_t)(r * 128) + (cc << 4));
            }
            #pragma unroll
            for (int mt = 0; mt < 2; mt++)
                #pragma unroll
                for (int nt = 0; nt < 8; nt++) {
                    const int p = nt >> 1, q = (nt & 1) * 2;
                    MMAF16(acc[mt][nt], ah[mt], bh[p][q], bh[p][q + 1]);
                }
        }
        __syncthreads();
        if (c + 2 < CH) issue_loads(c + 2);
    }

    // epilogue
    const int n0 = blockIdx.x * 128;
    const int r4 = lane >> 2, c2 = (lane & 3) * 2;
    #pragma unroll
    for (int mt = 0; mt < 2; mt++) {
        const int grow = rowA + wm + mt * 16 + r4;
        #pragma unroll
        for (int nt = 0; nt < 8; nt++) {
            const int gc = n0 + wn + nt * 8 + c2;
            const float bx = __ldg(bias + gc), by = __ldg(bias + gc + 1);
            float v00 = acc[mt][nt][0] + bx, v01 = acc[mt][nt][1] + by;
            float v10 = acc[mt][nt][2] + bx, v11 = acc[mt][nt][3] + by;
            if (MODE == 0) {
                *(uint32_t*)(Ch + (size_t)grow * N + gc)       = pack_h2(v00, v01);
                *(uint32_t*)(Ch + (size_t)(grow + 8) * N + gc) = pack_h2(v10, v11);
            }
            if (MODE == 1) {
                v00 = fmaxf(v00, 0.f); v01 = fmaxf(v01, 0.f);
                v10 = fmaxf(v10, 0.f); v11 = fmaxf(v11, 0.f);
                *(uint32_t*)(Ch + (size_t)grow * N + gc)       = pack_h2(v00, v01);
                *(uint32_t*)(Ch + (size_t)(grow + 8) * N + gc) = pack_h2(v10, v11);
            }
            if (MODE == 2) {
                const int which = gc >> 10;
                const int head  = (gc >> 6) & 15;
                const int d     = gc & 63;
                const int m0 = grow, m1 = grow + 8;
                const size_t o0 = (((size_t)((m0 >> 11) * 16 + head)) * 2048 + (m0 & 2047)) * 64 + d;
                const size_t o1 = (((size_t)((m1 >> 11) * 16 + head)) * 2048 + (m1 & 2047)) * 64 + d;
                const float sc = (which == 0) ? QSC_ : 1.f;
                __half* dst = (which == 0) ? Qh : (which == 1) ? Kh : Vh;
                *(uint32_t*)(dst + o0) = pack_h2(v00 * sc, v01 * sc);
                *(uint32_t*)(dst + o1) = pack_h2(v10 * sc, v11 * sc);
            }
        }
    }
}

// ---------------------------------------------------------------------------
// single-fp16 tensor-core flash attention, 2 CTAs/SM (validated R13)
// ---------------------------------------------------------------------------
#define ATT_SMEM (3 * 16384 + 3 * 256)

__global__ __launch_bounds__(256, 2)
void flash_attn_tc(const __half* __restrict__ Qh,
                   const __half* __restrict__ Kh, const __half* __restrict__ Vh,
                   const float* __restrict__ mask2,
                   __half* __restrict__ Oh)
{
    extern __shared__ char smem[];
    const uint32_t sb = smem_u32(smem);
    const int tid = threadIdx.x, wid = tid >> 5, lane = tid & 31;
    const int l7 = lane & 7, mi = lane >> 3;
    const int qblk = blockIdx.x, h = blockIdx.y, b = blockIdx.z;
    const size_t headoff = ((size_t)(b * H_ + h)) * S_ * DEP_;

    {
        const __half* qb = Qh + headoff + (size_t)qblk * 128 * DEP_;
        #pragma unroll
        for (int i = 0; i < 4; i++) {
            const int idx = tid + i * 256;
            const int row = idx >> 3, c16 = idx & 7;
            const uint32_t off = (uint32_t)(row * 128) + ((uint32_t)(c16 ^ (row & 7)) << 4);
            cp_async16(sb + off, qb + row * 64 + c16 * 8);
        }
        cp_commit();
        asm volatile("cp.async.wait_group 0;" ::: "memory");
        __syncthreads();
    }
    uint32_t qf[4][4];
    #pragma unroll
    for (int ks = 0; ks < 4; ks++) {
        const int r = wid * 16 + l7 + ((mi & 1) << 3);
        const uint32_t cc = (uint32_t)((2 * ks + (mi >> 1)) ^ (r & 7));
        LDMX4(qf[ks], sb + (uint32_t)(r * 128) + (cc << 4));
    }
    __syncthreads();

    auto issue = [&](int c) {
        const uint32_t stg = sb + (uint32_t)(c % 3) * 16384u;
        const size_t kbase = headoff + (size_t)c * 64 * DEP_;
        #pragma unroll
        for (int i = 0; i < 2; i++) {
            const int idx = tid + i * 256;
            const int row = idx >> 3, c16 = idx & 7;
            const uint32_t off = (uint32_t)(row * 128) + ((uint32_t)(c16 ^ (row & 7)) << 4);
            const size_t g = kbase + row * 64 + c16 * 8;
            cp_async16(stg + off,         Kh + g);
            cp_async16(stg + 8192u + off, Vh + g);
        }
        if (tid < 64)
            cp_async4(sb + 49152u + (uint32_t)(c % 3) * 256u + tid * 4,
                      mask2 + b * S_ + c * 64 + tid);
        cp_commit();
    };

    issue(0); issue(1); issue(2);

    float ctx[8][4];
    #pragma unroll
    for (int i = 0; i < 8; i++)
        #pragma unroll
        for (int j = 0; j < 4; j++) ctx[i][j] = 0.f;
    float sum0 = 0.f, sum1 = 0.f;

    const int CH = S_ / 64;
    for (int c = 0; c < CH; c++) {
        asm volatile("cp.async.wait_group 2;" ::: "memory");
        __syncthreads();
        const uint32_t stg = sb + (uint32_t)(c % 3) * 16384u;

        float lg[8][4];
        #pragma unroll
        for (int i = 0; i < 8; i++)
            #pragma unroll
            for (int j = 0; j < 4; j++) lg[i][j] = 0.f;

        #pragma unroll
        for (int ks = 0; ks < 4; ks++) {
            uint32_t khf[4][4];
            #pragma unroll
            for (int p = 0; p < 4; p++) {
                const int r = p * 16 + l7 + ((mi >> 1) << 3);
                const uint32_t cc = (uint32_t)((2 * ks + (mi & 1)) ^ (r & 7));
                LDMX4(khf[p], stg + (uint32_t)(r * 128) + (cc << 4));
            }
            #pragma unroll
            for (int nt = 0; nt < 8; nt++) {
                const int p = nt >> 1, q = (nt & 1) * 2;
                MMAF16(lg[nt], qf[ks], khf[p][q], khf[p][q + 1]);
            }
        }

        uint32_t pf[4][4];
        #pragma unroll
        for (int nt = 0; nt < 8; nt++) {
            const float2 mk = *(const float2*)(smem + 49152 + (c % 3) * 256
                                               + (nt * 8 + (lane & 3) * 2) * 4);
            const float p00 = fexp2(lg[nt][0] + mk.x);
            const float p01 = fexp2(lg[nt][1] + mk.y);
            const float p10 = fexp2(lg[nt][2] + mk.x);
            const float p11 = fexp2(lg[nt][3] + mk.y);
            sum0 += p00 + p01;
            sum1 += p10 + p11;
            const int kc = nt >> 1, q = (nt & 1) * 2;
            pf[kc][q]     = pack_h2(p00, p01);
            pf[kc][q + 1] = pack_h2(p10, p11);
        }

        #pragma unroll
        for (int kc = 0; kc < 4; kc++) {
            #pragma unroll
            for (int dp = 0; dp < 4; dp++) {
                const int r = kc * 16 + l7 + ((mi & 1) << 3);
                const uint32_t cc = (uint32_t)((dp * 2 + (mi >> 1)) ^ (r & 7));
                uint32_t vf[4];
                LDMX4T(vf, stg + 8192u + (uint32_t)(r * 128) + (cc << 4));
                MMAF16(ctx[2 * dp],     pf[kc], vf[0], vf[1]);
                MMAF16(ctx[2 * dp + 1], pf[kc], vf[2], vf[3]);
            }
        }
        __syncthreads();
        if (c + 3 < CH) issue(c + 3);
        else            cp_commit();
    }

    sum0 += __shfl_xor_sync(0xffffffffu, sum0, 1);
    sum0 += __shfl_xor_sync(0xffffffffu, sum0, 2);
    sum1 += __shfl_xor_sync(0xffffffffu, sum1, 1);
    sum1 += __shfl_xor_sync(0xffffffffu, sum1, 2);
    const float inv0 = 1.f / sum0, inv1 = 1.f / sum1;

    const int srow = qblk * 128 + wid * 16 + (lane >> 2);
    const size_t m0 = (size_t)b * S_ + srow;
    #pragma unroll
    for (int nt = 0; nt < 8; nt++) {
        const int col = h * 64 + nt * 8 + (lane & 3) * 2;
        *(uint32_t*)(Oh + m0 * D_ + col)       = pack_h2(ctx[nt][0] * inv0, ctx[nt][1] * inv0);
        *(uint32_t*)(Oh + (m0 + 8) * D_ + col) = pack_h2(ctx[nt][2] * inv1, ctx[nt][3] * inv1);
    }
}

// ---------------------------------------------------------------------------
// fused prep (single launch; validated R13)
// ---------------------------------------------------------------------------
__global__ void prep_all(
    const float* __restrict__ x, __half* __restrict__ xh,
    const float* __restrict__ wq, const float* __restrict__ wk,
    const float* __restrict__ wv, const float* __restrict__ wo,
    const float* __restrict__ w1, const float* __restrict__ w2,
    __half* __restrict__ qkvT, __half* __restrict__ woT,
    __half* __restrict__ w1T,  __half* __restrict__ w2T,
    const float* __restrict__ bq, const float* __restrict__ bk,
    const float* __restrict__ bv, float* __restrict__ bqkv,
    const float* __restrict__ msk, float* __restrict__ mask2)
{
    const int bid = blockIdx.x;
    const int t   = threadIdx.x;

    if (bid < 8192) {
        const size_t i = ((size_t)bid * 256 + t) * 4;
        float4 v = *(const float4*)(x + i);
        *(uint32_t*)(xh + i)     = pack_h2(v.x, v.y);
        *(uint32_t*)(xh + i + 2) = pack_h2(v.z, v.w);
        return;
    }
    if (bid < 14336) {
        const int tb = bid - 8192;
        const float* W; __half* Th;
        int K, N, rowOff, lb;
        if (tb < 512)       { W = wq; Th = qkvT; K = 1024; N = 1024; rowOff = 0;    lb = tb; }
        else if (tb < 1024) { W = wk; Th = qkvT; K = 1024; N = 1024; rowOff = 1024; lb = tb - 512; }
        else if (tb < 1536) { W = wv; Th = qkvT; K = 1024; N = 1024; rowOff = 2048; lb = tb - 1024; }
        else if (tb < 2048) { W = wo; Th = woT;  K = 1024; N = 1024; rowOff = 0;    lb = tb - 1536; }
        else if (tb < 4096) { W = w1; Th = w1T;  K = 1024; N = 4096; rowOff = 0;    lb = tb - 2048; }
        else                { W = w2; Th = w2T;  K = 4096; N = 1024; rowOff = 0;    lb = tb - 4096; }
        const int gx = K >> 5;
        const int k0 = (lb % gx) * 32, n0 = (lb / gx) * 64;

        __shared__ float tile[32][65];
        #pragma unroll
        for (int i = 0; i < 2; i++) {
            const int idx = t + i * 256;
            const int row = idx >> 4;
            const int c4  = (idx & 15) * 4;
            float4 v = *(const float4*)(W + (size_t)(k0 + row) * N + n0 + c4);
            tile[row][c4 + 0] = v.x; tile[row][c4 + 1] = v.y;
            tile[row][c4 + 2] = v.z; tile[row][c4 + 3] = v.w;
        }
        __syncthreads();
        #pragma unroll
        for (int i = 0; i < 4; i++) {
            const int idx = t + i * 256;
            const int kp  = idx & 15;
            const int n   = idx >> 4;
            const size_t o = (size_t)(rowOff + n0 + n) * K + k0 + kp * 2;
            *(uint32_t*)(Th + o) = pack_h2(tile[kp * 2][n], tile[kp * 2 + 1][n]);
        }
        return;
    }
    if (bid < 14339) {
        const int which = bid - 14336;
        const float* src = (which == 0) ? bq : (which == 1) ? bk : bv;
        #pragma unroll
        for (int i = 0; i < 4; i++)
            bqkv[which * 1024 + t + i * 256] = src[t + i * 256];
        return;
    }
    {
        const int i = (bid - 14339) * 256 + t;
        mask2[i] = msk[i] * (-1e9f * 1.44269504f);
    }
}

// ---------------------------------------------------------------------------
// out = LayerNorm(X + Yh) ; X fp32, Y fp16; optionally also write fp16
// ---------------------------------------------------------------------------
template <bool HOUT>
__global__ __launch_bounds__(256)
void add_layernorm(const float* __restrict__ X, const __half* __restrict__ Yh,
                   const float* __restrict__ gamma, const float* __restrict__ beta,
                   float* __restrict__ out, __half* __restrict__ Oh)
{
    __shared__ float red[8];
    __shared__ float s_mu, s_rstd;
    const int row = blockIdx.x;
    const int t   = threadIdx.x;

    const float4 a = *(const float4*)(X + (size_t)row * D_ + t * 4);
    const uint32_t y0 = *(const uint32_t*)(Yh + (size_t)row * D_ + t * 4);
    const uint32_t y1 = *(const uint32_t*)(Yh + (size_t)row * D_ + t * 4 + 2);
    const float2 yf0 = __half22float2(*reinterpret_cast<const __half2*>(&y0));
    const float2 yf1 = __half22float2(*reinterpret_cast<const __half2*>(&y1));
    float v0 = a.x + yf0.x, v1 = a.y + yf0.y, v2 = a.z + yf1.x, v3 = a.w + yf1.y;

    float s = v0 + v1 + v2 + v3;
    #pragma unroll
    for (int off = 16; off > 0; off >>= 1) s += __shfl_xor_sync(0xffffffffu, s, off);
    if ((t & 31) == 0) red[t >> 5] = s;
    __syncthreads();
    if (t < 32) {
        float w = (t < 8) ? red[t] : 0.f;
        #pragma unroll
        for (int off = 4; off > 0; off >>= 1) w += __shfl_xor_sync(0xffffffffu, w, off);
        if (t == 0) s_mu = w * (1.f / (float)D_);
    }
    __syncthreads();
    const float mu = s_mu;

    float d0 = v0 - mu, d1 = v1 - mu, d2 = v2 - mu, d3 = v3 - mu;
    float vs = d0*d0 + d1*d1 + d2*d2 + d3*d3;
    #pragma unroll
    for (int off = 16; off > 0; off >>= 1) vs += __shfl_xor_sync(0xffffffffu, vs, off);
    if ((t & 31) == 0) red[t >> 5] = vs;
    __syncthreads();
    if (t < 32) {
        float w = (t < 8) ? red[t] : 0.f;
        #pragma unroll
        for (int off = 4; off > 0; off >>= 1) w += __shfl_xor_sync(0xffffffffu, w, off);
        if (t == 0) s_rstd = rsqrtf(w * (1.f / (float)D_) + EPS_);
    }
    __syncthreads();
    const float rstd = s_rstd;

    const float4 g  = *(const float4*)(gamma + t * 4);
    const float4 bb = *(const float4*)(beta + t * 4);
    float4 o;
    o.x = d0 * rstd * g.x + bb.x;
    o.y = d1 * rstd * g.y + bb.y;
    o.z = d2 * rstd * g.z + bb.z;
    o.w = d3 * rstd * g.w + bb.w;
    *(float4*)(out + (size_t)row * D_ + t * 4) = o;

    if (HOUT) {
        const size_t base = (size_t)row * D_ + t * 4;
        *(uint32_t*)(Oh + base)     = pack_h2(o.x, o.y);
        *(uint32_t*)(Oh + base + 2) = pack_h2(o.z, o.w);
    }
}

// ---------------------------------------------------------------------------
// launcher
// ---------------------------------------------------------------------------
extern "C" void kernel_launch(void* const* d_in, const int* in_sizes, int n_in,
                              void* d_out, int out_size)
{
    const float* x   = (const float*)d_in[0];
    const float* msk = (const float*)d_in[1];
    const float* wq  = (const float*)d_in[2];
    const float* bq  = (const float*)d_in[3];
    const float* wk  = (const float*)d_in[4];
    const float* bk  = (const float*)d_in[5];
    const float* wv  = (const float*)d_in[6];
    const float* bv  = (const float*)d_in[7];
    const float* wo  = (const float*)d_in[8];
    const float* bo  = (const float*)d_in[9];
    const float* w1  = (const float*)d_in[10];
    const float* b1  = (const float*)d_in[11];
    const float* w2  = (const float*)d_in[12];
    const float* b2  = (const float*)d_in[13];
    const float* g1  = (const float*)d_in[14];
    const float* be1 = (const float*)d_in[15];
    const float* g2  = (const float*)d_in[16];
    const float* be2 = (const float*)d_in[17];
    float* out = (float*)d_out;

    __half *xh, *wqkvT, *woT, *w1T, *w2T, *qh, *kh, *vh, *ctxh, *tmph, *o1h, *ffnh;
    float *bqkv, *o1, *mask2;
    cudaGetSymbolAddress((void**)&xh, g_xh);
    cudaGetSymbolAddress((void**)&wqkvT, g_wqkvT);
    cudaGetSymbolAddress((void**)&bqkv, g_bqkv);
    cudaGetSymbolAddress((void**)&woT, g_woT);
    cudaGetSymbolAddress((void**)&w1T, g_w1T);
    cudaGetSymbolAddress((void**)&w2T, g_w2T);
    cudaGetSymbolAddress((void**)&qh, g_qh);
    cudaGetSymbolAddress((void**)&kh, g_kh);
    cudaGetSymbolAddress((void**)&vh, g_vh);
    cudaGetSymbolAddress((void**)&mask2, g_mask2);
    cudaGetSymbolAddress((void**)&ctxh, g_ctxh);
    cudaGetSymbolAddress((void**)&tmph, g_tmph);
    cudaGetSymbolAddress((void**)&o1, g_o1);
    cudaGetSymbolAddress((void**)&o1h, g_o1h);
    cudaGetSymbolAddress((void**)&ffnh, g_ffnh);

    cudaFuncSetAttribute(gemm_mma<0>, cudaFuncAttributeMaxDynamicSharedMemorySize, GEMM_SMEM);
    cudaFuncSetAttribute(gemm_mma<1>, cudaFuncAttributeMaxDynamicSharedMemorySize, GEMM_SMEM);
    cudaFuncSetAttribute(gemm_mma<2>, cudaFuncAttributeMaxDynamicSharedMemorySize, GEMM_SMEM);
    cudaFuncSetAttribute(flash_attn_tc, cudaFuncAttributeMaxDynamicSharedMemorySize, ATT_SMEM);

    // fused prep (single launch)
    prep_all<<<14371, 256>>>(x, xh, wq, wk, wv, wo, w1, w2,
                             wqkvT, woT, w1T, w2T,
                             bq, bk, bv, bqkv, msk, mask2);

    // fused QKV projection -> Q/K/V single fp16, head-major (Q pre-scaled)
    gemm_mma<2><<<dim3(24, 128), 128, GEMM_SMEM>>>(
        xh, wqkvT, bqkv, nullptr, qh, kh, vh, M_, 3072, D_);

    // fp16 tensor-core attention -> fp16 ctx (2 CTAs/SM)
    flash_attn_tc<<<dim3(S_ / 128, H_, B_), 256, ATT_SMEM>>>(
        qh, kh, vh, mask2, ctxh);

    // output projection (fp16 out) + LN1
    gemm_mma<0><<<dim3(8, 128), 128, GEMM_SMEM>>>(
        ctxh, woT, bo, tmph, nullptr, nullptr, nullptr, M_, D_, D_);
    add_layernorm<true><<<M_, 256>>>(x, tmph, g1, be1, o1, o1h);

    // FFN
    gemm_mma<1><<<dim3(32, 128), 128, GEMM_SMEM>>>(
        o1h, w1T, b1, ffnh, nullptr, nullptr, nullptr, M_, DFF_, D_);
    gemm_mma<0><<<dim3(8, 128), 128, GEMM_SMEM>>>(
        ffnh, w2T, b2, tmph, nullptr, nullptr, nullptr, M_, D_, DFF_);

    // LN2 -> out
    add_layernorm<false><<<M_, 256>>>(o1, tmph, g2, be2, out, nullptr);
}

// round 16
// speedup vs baseline: 1.0373x; 1.0373x over previous
#include <cuda_runtime.h>
#include <cuda_bf16.h>
#include <cuda_fp16.h>
#include <math.h>
#include <stdint.h>

#define B_   4
#define S_   2048
#define D_   1024
#define H_   16
#define DEP_ 64
#define DFF_ 4096
#define M_   (B_ * S_)
#define EPS_ 1e-6f
#define QSC_ 0.180336884f   /* 0.125 * log2(e) */

// ---------------- scratch (static device globals) ----------------
__device__ __half g_xh[M_ * D_];
__device__ __half g_wqkvT[3 * D_ * D_];
__device__ float  g_bqkv[3 * D_];
__device__ __half g_woT[D_ * D_];
__device__ __half g_w1T[DFF_ * D_];
__device__ __half g_w2T[D_ * DFF_];
__device__ __half g_qh[M_ * D_];
__device__ __half g_kh[M_ * D_];
__device__ __half g_vh[M_ * D_];
__device__ float  g_mask2[B_ * S_];
__device__ __half g_ctxh[M_ * D_];
__device__ __half g_tmph[M_ * D_];
__device__ __half g_o1h[M_ * D_];
__device__ __half g_ffnh[M_ * DFF_];

// ---------------- PTX helpers (base-arch only) ----------------
__device__ __forceinline__ uint32_t smem_u32(const void* p) {
    uint32_t a;
    asm("{ .reg .u64 t; cvta.to.shared.u64 t, %1; cvt.u32.u64 %0, t; }" : "=r"(a) : "l"(p));
    return a;
}
__device__ __forceinline__ void cp_async16(uint32_t dst, const void* src) {
    asm volatile("cp.async.cg.shared.global [%0], [%1], 16;" :: "r"(dst), "l"(src));
}
__device__ __forceinline__ void cp_async4(uint32_t dst, const void* src) {
    asm volatile("cp.async.ca.shared.global [%0], [%1], 4;" :: "r"(dst), "l"(src));
}
__device__ __forceinline__ void cp_commit() {
    asm volatile("cp.async.commit_group;" ::: "memory");
}
#define LDMX4(r, addr)                                                           \
    asm volatile("ldmatrix.sync.aligned.m8n8.x4.shared.b16 {%0,%1,%2,%3}, [%4];" \
        : "=r"((r)[0]), "=r"((r)[1]), "=r"((r)[2]), "=r"((r)[3]) : "r"(addr))
#define LDMX4T(r, addr)                                                          \
    asm volatile("ldmatrix.sync.aligned.m8n8.x4.trans.shared.b16 {%0,%1,%2,%3}, [%4];" \
        : "=r"((r)[0]), "=r"((r)[1]), "=r"((r)[2]), "=r"((r)[3]) : "r"(addr))
#define MMAF16(d, a, b0, b1)                                                     \
    asm volatile("mma.sync.aligned.m16n8k16.row.col.f32.f16.f16.f32 "            \
        "{%0,%1,%2,%3}, {%4,%5,%6,%7}, {%8,%9}, {%0,%1,%2,%3};"                  \
        : "+f"((d)[0]), "+f"((d)[1]), "+f"((d)[2]), "+f"((d)[3])                 \
        : "r"((a)[0]), "r"((a)[1]), "r"((a)[2]), "r"((a)[3]), "r"(b0), "r"(b1))

__device__ __forceinline__ uint32_t pack_h2(float a, float b) {
    __half2 v = __floats2half2_rn(a, b);
    return *reinterpret_cast<uint32_t*>(&v);
}
// fast 2^t on the FMA pipe (no MUFU); rel err ~4e-5
__device__ __forceinline__ float fexp2(float t) {
    t = fmaxf(t, -126.f);
    float r = t + 12582912.f;
    float f = t - (r - 12582912.f);
    uint32_t ib = (__float_as_uint(r) << 23) + 0x3F800000u;
    float p = fmaf(f, 0.00961813f, 0.05550411f);
    p = fmaf(f, p, 0.24022651f);
    p = fmaf(f, p, 0.69314718f);
    p = fmaf(f, p, 1.0f);
    return __uint_as_float(ib) * p;
}

// ---------------------------------------------------------------------------
// single-fp16 GEMM: C = A[M,K] @ B^T[N,K] + bias, 1 MMA/step.
// Tile 64x128 x K64, 2-stage pipeline; 128 threads, 2x2 warp grid (32x64
// warp tiles), 3 CTAs/SM. (R14-validated configuration — best measured.)
// Stage (24KB): A(8K) | B(16K); 128B rows, XOR-swizzled.
// MODE: 0 = fp16 out; 1 = relu + fp16 out; 2 = fused-QKV epilogue.
// ---------------------------------------------------------------------------
#define ST_       24576
#define GEMM_SMEM (2 * ST_)

template <int MODE>
__global__ __launch_bounds__(128, 3)
void gemm_mma(const __half* __restrict__ A, const __half* __restrict__ Bw,
              const float* __restrict__ bias,
              __half* __restrict__ Ch,
              __half* __restrict__ Qh, __half* __restrict__ Kh, __half* __restrict__ Vh,
              int M, int N, int K)
{
    extern __shared__ char smem[];
    const uint32_t sb = smem_u32(smem);
    const int tid  = threadIdx.x;
    const int wid  = tid >> 5;
    const int lane = tid & 31;

    const int rowA  = blockIdx.y * 64;
    const int rowBn = blockIdx.x * 128;
    const int CH    = K >> 6;

    auto issue_loads = [&](int c) {
        const int k0 = c << 6;
        const uint32_t stg = sb + (uint32_t)(c & 1) * ST_;
        #pragma unroll
        for (int j = 0; j < 12; j++) {
            const __half* base;
            uint32_t doff;
            int rel, rb;
            if (j < 4) { base = A;  doff = 0u;    rel = j * 128 + tid;       rb = rowA;  }
            else       { base = Bw; doff = 8192u; rel = (j - 4) * 128 + tid; rb = rowBn; }
            const int row = rel >> 3, c16 = rel & 7;
            const uint32_t off = (uint32_t)(row * 128) + ((uint32_t)(c16 ^ (row & 7)) << 4);
            cp_async16(stg + doff + off, base + (size_t)(rb + row) * K + k0 + c16 * 8);
        }
        cp_commit();
    };

    issue_loads(0);
    issue_loads(1);

    float acc[2][8][4];
    #pragma unroll
    for (int i = 0; i < 2; i++)
        #pragma unroll
        for (int j = 0; j < 8; j++)
            #pragma unroll
            for (int r = 0; r < 4; r++) acc[i][j][r] = 0.f;

    const int wm = (wid >> 1) * 32;   // 2 warp rows x 32
    const int wn = (wid & 1) * 64;    // 2 warp cols x 64
    const int l7 = lane & 7;
    const int mi = lane >> 3;

    for (int c = 0; c < CH; c++) {
        if (c + 1 < CH) { asm volatile("cp.async.wait_group 1;" ::: "memory"); }
        else            { asm volatile("cp.async.wait_group 0;" ::: "memory"); }
        __syncthreads();

        const uint32_t stg = sb + (uint32_t)(c & 1) * ST_;
        #pragma unroll
        for (int ks = 0; ks < 4; ks++) {
            uint32_t ah[2][4], bh[4][4];
            #pragma unroll
            for (int mt = 0; mt < 2; mt++) {
                const int r = wm + mt * 16 + l7 + ((mi & 1) << 3);
                const uint32_t cc = (uint32_t)((2 * ks + (mi >> 1)) ^ (r & 7));
                LDMX4(ah[mt], stg + (uint32_t)(r * 128) + (cc << 4));
            }
            #pragma unroll
            for (int p = 0; p < 4; p++) {
                const int r = wn + p * 16 + l7 + ((mi >> 1) << 3);
                const uint32_t cc = (uint32_t)((2 * ks + (mi & 1)) ^ (r & 7));
                LDMX4(bh[p], stg + 8192u + (uint32_t)(r * 128) + (cc << 4));
            }
            #pragma unroll
            for (int mt = 0; mt < 2; mt++)
                #pragma unroll
                for (int nt = 0; nt < 8; nt++) {
                    const int p = nt >> 1, q = (nt & 1) * 2;
                    MMAF16(acc[mt][nt], ah[mt], bh[p][q], bh[p][q + 1]);
                }
        }
        __syncthreads();
        if (c + 2 < CH) issue_loads(c + 2);
    }

    // epilogue
    const int n0 = blockIdx.x * 128;
    const int r4 = lane >> 2, c2 = (lane & 3) * 2;
    #pragma unroll
    for (int mt = 0; mt < 2; mt++) {
        const int grow = rowA + wm + mt * 16 + r4;
        #pragma unroll
        for (int nt = 0; nt < 8; nt++) {
            const int gc = n0 + wn + nt * 8 + c2;
            const float bx = __ldg(bias + gc), by = __ldg(bias + gc + 1);
            float v00 = acc[mt][nt][0] + bx, v01 = acc[mt][nt][1] + by;
            float v10 = acc[mt][nt][2] + bx, v11 = acc[mt][nt][3] + by;
            if (MODE == 0) {
                *(uint32_t*)(Ch + (size_t)grow * N + gc)       = pack_h2(v00, v01);
                *(uint32_t*)(Ch + (size_t)(grow + 8) * N + gc) = pack_h2(v10, v11);
            }
            if (MODE == 1) {
                v00 = fmaxf(v00, 0.f); v01 = fmaxf(v01, 0.f);
                v10 = fmaxf(v10, 0.f); v11 = fmaxf(v11, 0.f);
                *(uint32_t*)(Ch + (size_t)grow * N + gc)       = pack_h2(v00, v01);
                *(uint32_t*)(Ch + (size_t)(grow + 8) * N + gc) = pack_h2(v10, v11);
            }
            if (MODE == 2) {
                const int which = gc >> 10;
                const int head  = (gc >> 6) & 15;
                const int d     = gc & 63;
                const int m0 = grow, m1 = grow + 8;
                const size_t o0 = (((size_t)((m0 >> 11) * 16 + head)) * 2048 + (m0 & 2047)) * 64 + d;
                const size_t o1 = (((size_t)((m1 >> 11) * 16 + head)) * 2048 + (m1 & 2047)) * 64 + d;
                const float sc = (which == 0) ? QSC_ : 1.f;
                __half* dst = (which == 0) ? Qh : (which == 1) ? Kh : Vh;
                *(uint32_t*)(dst + o0) = pack_h2(v00 * sc, v01 * sc);
                *(uint32_t*)(dst + o1) = pack_h2(v10 * sc, v11 * sc);
            }
        }
    }
}

// ---------------------------------------------------------------------------
// single-fp16 tensor-core flash attention, 2 CTAs/SM (validated R13)
// ---------------------------------------------------------------------------
#define ATT_SMEM (3 * 16384 + 3 * 256)

__global__ __launch_bounds__(256, 2)
void flash_attn_tc(const __half* __restrict__ Qh,
                   const __half* __restrict__ Kh, const __half* __restrict__ Vh,
                   const float* __restrict__ mask2,
                   __half* __restrict__ Oh)
{
    extern __shared__ char smem[];
    const uint32_t sb = smem_u32(smem);
    const int tid = threadIdx.x, wid = tid >> 5, lane = tid & 31;
    const int l7 = lane & 7, mi = lane >> 3;
    const int qblk = blockIdx.x, h = blockIdx.y, b = blockIdx.z;
    const size_t headoff = ((size_t)(b * H_ + h)) * S_ * DEP_;

    {
        const __half* qb = Qh + headoff + (size_t)qblk * 128 * DEP_;
        #pragma unroll
        for (int i = 0; i < 4; i++) {
            const int idx = tid + i * 256;
            const int row = idx >> 3, c16 = idx & 7;
            const uint32_t off = (uint32_t)(row * 128) + ((uint32_t)(c16 ^ (row & 7)) << 4);
            cp_async16(sb + off, qb + row * 64 + c16 * 8);
        }
        cp_commit();
        asm volatile("cp.async.wait_group 0;" ::: "memory");
        __syncthreads();
    }
    uint32_t qf[4][4];
    #pragma unroll
    for (int ks = 0; ks < 4; ks++) {
        const int r = wid * 16 + l7 + ((mi & 1) << 3);
        const uint32_t cc = (uint32_t)((2 * ks + (mi >> 1)) ^ (r & 7));
        LDMX4(qf[ks], sb + (uint32_t)(r * 128) + (cc << 4));
    }
    __syncthreads();

    auto issue = [&](int c) {
        const uint32_t stg = sb + (uint32_t)(c % 3) * 16384u;
        const size_t kbase = headoff + (size_t)c * 64 * DEP_;
        #pragma unroll
        for (int i = 0; i < 2; i++) {
            const int idx = tid + i * 256;
            const int row = idx >> 3, c16 = idx & 7;
            const uint32_t off = (uint32_t)(row * 128) + ((uint32_t)(c16 ^ (row & 7)) << 4);
            const size_t g = kbase + row * 64 + c16 * 8;
            cp_async16(stg + off,         Kh + g);
            cp_async16(stg + 8192u + off, Vh + g);
        }
        if (tid < 64)
            cp_async4(sb + 49152u + (uint32_t)(c % 3) * 256u + tid * 4,
                      mask2 + b * S_ + c * 64 + tid);
        cp_commit();
    };

    issue(0); issue(1); issue(2);

    float ctx[8][4];
    #pragma unroll
    for (int i = 0; i < 8; i++)
        #pragma unroll
        for (int j = 0; j < 4; j++) ctx[i][j] = 0.f;
    float sum0 = 0.f, sum1 = 0.f;

    const int CH = S_ / 64;
    for (int c = 0; c < CH; c++) {
        asm volatile("cp.async.wait_group 2;" ::: "memory");
        __syncthreads();
        const uint32_t stg = sb + (uint32_t)(c % 3) * 16384u;

        float lg[8][4];
        #pragma unroll
        for (int i = 0; i < 8; i++)
            #pragma unroll
            for (int j = 0; j < 4; j++) lg[i][j] = 0.f;

        #pragma unroll
        for (int ks = 0; ks < 4; ks++) {
            uint32_t khf[4][4];
            #pragma unroll
            for (int p = 0; p < 4; p++) {
                const int r = p * 16 + l7 + ((mi >> 1) << 3);
                const uint32_t cc = (uint32_t)((2 * ks + (mi & 1)) ^ (r & 7));
                LDMX4(khf[p], stg + (uint32_t)(r * 128) + (cc << 4));
            }
            #pragma unroll
            for (int nt = 0; nt < 8; nt++) {
                const int p = nt >> 1, q = (nt & 1) * 2;
                MMAF16(lg[nt], qf[ks], khf[p][q], khf[p][q + 1]);
            }
        }

        uint32_t pf[4][4];
        #pragma unroll
        for (int nt = 0; nt < 8; nt++) {
            const float2 mk = *(const float2*)(smem + 49152 + (c % 3) * 256
                                               + (nt * 8 + (lane & 3) * 2) * 4);
            const float p00 = fexp2(lg[nt][0] + mk.x);
            const float p01 = fexp2(lg[nt][1] + mk.y);
            const float p10 = fexp2(lg[nt][2] + mk.x);
            const float p11 = fexp2(lg[nt][3] + mk.y);
            sum0 += p00 + p01;
            sum1 += p10 + p11;
            const int kc = nt >> 1, q = (nt & 1) * 2;
            pf[kc][q]     = pack_h2(p00, p01);
            pf[kc][q + 1] = pack_h2(p10, p11);
        }

        #pragma unroll
        for (int kc = 0; kc < 4; kc++) {
            #pragma unroll
            for (int dp = 0; dp < 4; dp++) {
                const int r = kc * 16 + l7 + ((mi & 1) << 3);
                const uint32_t cc = (uint32_t)((dp * 2 + (mi >> 1)) ^ (r & 7));
                uint32_t vf[4];
                LDMX4T(vf, stg + 8192u + (uint32_t)(r * 128) + (cc << 4));
                MMAF16(ctx[2 * dp],     pf[kc], vf[0], vf[1]);
                MMAF16(ctx[2 * dp + 1], pf[kc], vf[2], vf[3]);
            }
        }
        __syncthreads();
        if (c + 3 < CH) issue(c + 3);
        else            cp_commit();
    }

    sum0 += __shfl_xor_sync(0xffffffffu, sum0, 1);
    sum0 += __shfl_xor_sync(0xffffffffu, sum0, 2);
    sum1 += __shfl_xor_sync(0xffffffffu, sum1, 1);
    sum1 += __shfl_xor_sync(0xffffffffu, sum1, 2);
    const float inv0 = 1.f / sum0, inv1 = 1.f / sum1;

    const int srow = qblk * 128 + wid * 16 + (lane >> 2);
    const size_t m0 = (size_t)b * S_ + srow;
    #pragma unroll
    for (int nt = 0; nt < 8; nt++) {
        const int col = h * 64 + nt * 8 + (lane & 3) * 2;
        *(uint32_t*)(Oh + m0 * D_ + col)       = pack_h2(ctx[nt][0] * inv0, ctx[nt][1] * inv0);
        *(uint32_t*)(Oh + (m0 + 8) * D_ + col) = pack_h2(ctx[nt][2] * inv1, ctx[nt][3] * inv1);
    }
}

// ---------------------------------------------------------------------------
// fused prep (single launch; validated R13)
// ---------------------------------------------------------------------------
__global__ void prep_all(
    const float* __restrict__ x, __half* __restrict__ xh,
    const float* __restrict__ wq, const float* __restrict__ wk,
    const float* __restrict__ wv, const float* __restrict__ wo,
    const float* __restrict__ w1, const float* __restrict__ w2,
    __half* __restrict__ qkvT, __half* __restrict__ woT,
    __half* __restrict__ w1T,  __half* __restrict__ w2T,
    const float* __restrict__ bq, const float* __restrict__ bk,
    const float* __restrict__ bv, float* __restrict__ bqkv,
    const float* __restrict__ msk, float* __restrict__ mask2)
{
    const int bid = blockIdx.x;
    const int t   = threadIdx.x;

    if (bid < 8192) {
        const size_t i = ((size_t)bid * 256 + t) * 4;
        float4 v = *(const float4*)(x + i);
        *(uint32_t*)(xh + i)     = pack_h2(v.x, v.y);
        *(uint32_t*)(xh + i + 2) = pack_h2(v.z, v.w);
        return;
    }
    if (bid < 14336) {
        const int tb = bid - 8192;
        const float* W; __half* Th;
        int K, N, rowOff, lb;
        if (tb < 512)       { W = wq; Th = qkvT; K = 1024; N = 1024; rowOff = 0;    lb = tb; }
        else if (tb < 1024) { W = wk; Th = qkvT; K = 1024; N = 1024; rowOff = 1024; lb = tb - 512; }
        else if (tb < 1536) { W = wv; Th = qkvT; K = 1024; N = 1024; rowOff = 2048; lb = tb - 1024; }
        else if (tb < 2048) { W = wo; Th = woT;  K = 1024; N = 1024; rowOff = 0;    lb = tb - 1536; }
        else if (tb < 4096) { W = w1; Th = w1T;  K = 1024; N = 4096; rowOff = 0;    lb = tb - 2048; }
        else                { W = w2; Th = w2T;  K = 4096; N = 1024; rowOff = 0;    lb = tb - 4096; }
        const int gx = K >> 5;
        const int k0 = (lb % gx) * 32, n0 = (lb / gx) * 64;

        __shared__ float tile[32][65];
        #pragma unroll
        for (int i = 0; i < 2; i++) {
            const int idx = t + i * 256;
            const int row = idx >> 4;
            const int c4  = (idx & 15) * 4;
            float4 v = *(const float4*)(W + (size_t)(k0 + row) * N + n0 + c4);
            tile[row][c4 + 0] = v.x; tile[row][c4 + 1] = v.y;
            tile[row][c4 + 2] = v.z; tile[row][c4 + 3] = v.w;
        }
        __syncthreads();
        #pragma unroll
        for (int i = 0; i < 4; i++) {
            const int idx = t + i * 256;
            const int kp  = idx & 15;
            const int n   = idx >> 4;
            const size_t o = (size_t)(rowOff + n0 + n) * K + k0 + kp * 2;
            *(uint32_t*)(Th + o) = pack_h2(tile[kp * 2][n], tile[kp * 2 + 1][n]);
        }
        return;
    }
    if (bid < 14339) {
        const int which = bid - 14336;
        const float* src = (which == 0) ? bq : (which == 1) ? bk : bv;
        #pragma unroll
        for (int i = 0; i < 4; i++)
            bqkv[which * 1024 + t + i * 256] = src[t + i * 256];
        return;
    }
    {
        const int i = (bid - 14339) * 256 + t;
        mask2[i] = msk[i] * (-1e9f * 1.44269504f);
    }
}

// ---------------------------------------------------------------------------
// LayerNorm(X + Yh): XF32 selects residual-input dtype; F32OUT writes d_out.
// LN1: <true,false>  x fp32 + tmph fp16 -> o1h fp16 only.
// LN2: <false,true>  o1h fp16 + tmph fp16 -> out fp32.
// ---------------------------------------------------------------------------
template <bool XF32, bool F32OUT>
__global__ __launch_bounds__(256)
void add_layernorm(const float* __restrict__ Xf, const __half* __restrict__ Xh,
                   const __half* __restrict__ Yh,
                   const float* __restrict__ gamma, const float* __restrict__ beta,
                   float* __restrict__ out, __half* __restrict__ Oh)
{
    __shared__ float red[8];
    __shared__ float s_mu, s_rstd;
    const int row = blockIdx.x;
    const int t   = threadIdx.x;
    const size_t base = (size_t)row * D_ + t * 4;

    float x0, x1, x2, x3;
    if (XF32) {
        const float4 a = *(const float4*)(Xf + base);
        x0 = a.x; x1 = a.y; x2 = a.z; x3 = a.w;
    } else {
        const uint32_t a0 = *(const uint32_t*)(Xh + base);
        const uint32_t a1 = *(const uint32_t*)(Xh + base + 2);
        const float2 f0 = __half22float2(*reinterpret_cast<const __half2*>(&a0));
        const float2 f1 = __half22float2(*reinterpret_cast<const __half2*>(&a1));
        x0 = f0.x; x1 = f0.y; x2 = f1.x; x3 = f1.y;
    }
    const uint32_t y0 = *(const uint32_t*)(Yh + base);
    const uint32_t y1 = *(const uint32_t*)(Yh + base + 2);
    const float2 yf0 = __half22float2(*reinterpret_cast<const __half2*>(&y0));
    const float2 yf1 = __half22float2(*reinterpret_cast<const __half2*>(&y1));
    float v0 = x0 + yf0.x, v1 = x1 + yf0.y, v2 = x2 + yf1.x, v3 = x3 + yf1.y;

    float s = v0 + v1 + v2 + v3;
    #pragma unroll
    for (int off = 16; off > 0; off >>= 1) s += __shfl_xor_sync(0xffffffffu, s, off);
    if ((t & 31) == 0) red[t >> 5] = s;
    __syncthreads();
    if (t < 32) {
        float w = (t < 8) ? red[t] : 0.f;
        #pragma unroll
        for (int off = 4; off > 0; off >>= 1) w += __shfl_xor_sync(0xffffffffu, w, off);
        if (t == 0) s_mu = w * (1.f / (float)D_);
    }
    __syncthreads();
    const float mu = s_mu;

    float d0 = v0 - mu, d1 = v1 - mu, d2 = v2 - mu, d3 = v3 - mu;
    float vs = d0*d0 + d1*d1 + d2*d2 + d3*d3;
    #pragma unroll
    for (int off = 16; off > 0; off >>= 1) vs += __shfl_xor_sync(0xffffffffu, vs, off);
    if ((t & 31) == 0) red[t >> 5] = vs;
    __syncthreads();
    if (t < 32) {
        float w = (t < 8) ? red[t] : 0.f;
        #pragma unroll
        for (int off = 4; off > 0; off >>= 1) w += __shfl_xor_sync(0xffffffffu, w, off);
        if (t == 0) s_rstd = rsqrtf(w * (1.f / (float)D_) + EPS_);
    }
    __syncthreads();
    const float rstd = s_rstd;

    const float4 g  = *(const float4*)(gamma + t * 4);
    const float4 bb = *(const float4*)(beta + t * 4);
    float4 o;
    o.x = d0 * rstd * g.x + bb.x;
    o.y = d1 * rstd * g.y + bb.y;
    o.z = d2 * rstd * g.z + bb.z;
    o.w = d3 * rstd * g.w + bb.w;

    if (F32OUT) {
        *(float4*)(out + base) = o;
    } else {
        *(uint32_t*)(Oh + base)     = pack_h2(o.x, o.y);
        *(uint32_t*)(Oh + base + 2) = pack_h2(o.z, o.w);
    }
}

// ---------------------------------------------------------------------------
// launcher
// ---------------------------------------------------------------------------
extern "C" void kernel_launch(void* const* d_in, const int* in_sizes, int n_in,
                              void* d_out, int out_size)
{
    const float* x   = (const float*)d_in[0];
    const float* msk = (const float*)d_in[1];
    const float* wq  = (const float*)d_in[2];
    const float* bq  = (const float*)d_in[3];
    const float* wk  = (const float*)d_in[4];
    const float* bk  = (const float*)d_in[5];
    const float* wv  = (const float*)d_in[6];
    const float* bv  = (const float*)d_in[7];
    const float* wo  = (const float*)d_in[8];
    const float* bo  = (const float*)d_in[9];
    const float* w1  = (const float*)d_in[10];
    const float* b1  = (const float*)d_in[11];
    const float* w2  = (const float*)d_in[12];
    const float* b2  = (const float*)d_in[13];
    const float* g1  = (const float*)d_in[14];
    const float* be1 = (const float*)d_in[15];
    const float* g2  = (const float*)d_in[16];
    const float* be2 = (const float*)d_in[17];
    float* out = (float*)d_out;

    __half *xh, *wqkvT, *woT, *w1T, *w2T, *qh, *kh, *vh, *ctxh, *tmph, *o1h, *ffnh;
    float *bqkv, *mask2;
    cudaGetSymbolAddress((void**)&xh, g_xh);
    cudaGetSymbolAddress((void**)&wqkvT, g_wqkvT);
    cudaGetSymbolAddress((void**)&bqkv, g_bqkv);
    cudaGetSymbolAddress((void**)&woT, g_woT);
    cudaGetSymbolAddress((void**)&w1T, g_w1T);
    cudaGetSymbolAddress((void**)&w2T, g_w2T);
    cudaGetSymbolAddress((void**)&qh, g_qh);
    cudaGetSymbolAddress((void**)&kh, g_kh);
    cudaGetSymbolAddress((void**)&vh, g_vh);
    cudaGetSymbolAddress((void**)&mask2, g_mask2);
    cudaGetSymbolAddress((void**)&ctxh, g_ctxh);
    cudaGetSymbolAddress((void**)&tmph, g_tmph);
    cudaGetSymbolAddress((void**)&o1h, g_o1h);
    cudaGetSymbolAddress((void**)&ffnh, g_ffnh);

    cudaFuncSetAttribute(gemm_mma<0>, cudaFuncAttributeMaxDynamicSharedMemorySize, GEMM_SMEM);
    cudaFuncSetAttribute(gemm_mma<1>, cudaFuncAttributeMaxDynamicSharedMemorySize, GEMM_SMEM);
    cudaFuncSetAttribute(gemm_mma<2>, cudaFuncAttributeMaxDynamicSharedMemorySize, GEMM_SMEM);
    cudaFuncSetAttribute(flash_attn_tc, cudaFuncAttributeMaxDynamicSharedMemorySize, ATT_SMEM);

    // fused prep (single launch)
    prep_all<<<14371, 256>>>(x, xh, wq, wk, wv, wo, w1, w2,
                             wqkvT, woT, w1T, w2T,
                             bq, bk, bv, bqkv, msk, mask2);

    // fused QKV projection -> Q/K/V single fp16, head-major (Q pre-scaled)
    gemm_mma<2><<<dim3(24, 128), 128, GEMM_SMEM>>>(
        xh, wqkvT, bqkv, nullptr, qh, kh, vh, M_, 3072, D_);

    // fp16 tensor-core attention -> fp16 ctx (2 CTAs/SM)
    flash_attn_tc<<<dim3(S_ / 128, H_, B_), 256, ATT_SMEM>>>(
        qh, kh, vh, mask2, ctxh);

    // output projection (fp16 out) + LN1 (fp16-only output)
    gemm_mma<0><<<dim3(8, 128), 128, GEMM_SMEM>>>(
        ctxh, woT, bo, tmph, nullptr, nullptr, nullptr, M_, D_, D_);
    add_layernorm<true, false><<<M_, 256>>>(x, nullptr, tmph, g1, be1, nullptr, o1h);

    // FFN
    gemm_mma<1><<<dim3(32, 128), 128, GEMM_SMEM>>>(
        o1h, w1T, b1, ffnh, nullptr, nullptr, nullptr, M_, DFF_, D_);
    gemm_mma<0><<<dim3(8, 128), 128, GEMM_SMEM>>>(
        ffnh, w2T, b2, tmph, nullptr, nullptr, nullptr, M_, D_, DFF_);

    // LN2 (fp16 residual input) -> fp32 out
    add_layernorm<false, true><<<M_, 256>>>(nullptr, o1h, tmph, g2, be2, out, nullptr);
}